// round 14
// baseline (speedup 1.0000x reference)
#include <cuda_runtime.h>
#include <cstdint>

// Problem constants (from reference)
#define NNODES 100000
#define NEDGES 600000
#define NHEADS 8
#define NDIM   16
#define NTGT   20000
#define ROW    (NHEADS * NDIM)   // 128 floats per node/edge row

// Scratch: per-node aggregated features + "is-target" flag.
// Flags are set-only and the target set is identical every launch; nft target
// rows are re-zeroed at the start of every launch by k_prep.
__device__ float         g_nft[(size_t)NNODES * ROW];
__device__ unsigned char g_flag[NNODES];

// ---------------------------------------------------------------------------
// K1: zero nft rows for target nodes, set flags. 1 warp per target.
// ---------------------------------------------------------------------------
__global__ void k_prep(const int* __restrict__ target_idx, int T) {
    int w = (blockIdx.x * blockDim.x + threadIdx.x) >> 5;
    int lane = threadIdx.x & 31;
    if (w >= T) return;
    int n = target_idx[w];
    float4 z = make_float4(0.f, 0.f, 0.f, 0.f);
    *reinterpret_cast<float4*>(&g_nft[(size_t)n * ROW + lane * 4]) = z;
    if (lane == 0) g_flag[n] = 1;
}

// ---------------------------------------------------------------------------
// K2: 8 edges per warp. All memory issued up front: 2 int4 dst loads,
// 8 sequential eft row streams (512B each), 8 L2-resident node row gathers,
// 8 flag bytes -> ~24 outstanding loads/warp for deep DRAM pipelining.
// Then 8 overlapping dot+softmax shuffle chains, two coalesced 128B 'a'
// stores, and predicated vec4 RED scatter for target nodes (~18%).
// Lane = one float4 chunk of the 128-float row; head = lane>>2.
// ---------------------------------------------------------------------------
__global__ void __launch_bounds__(256) k_edge(const float* __restrict__ node,
                                              const float* __restrict__ eft,
                                              const int*   __restrict__ dst,
                                              float* __restrict__ a_out) {
    const int lane = threadIdx.x & 31;
    const int warp = (blockIdx.x * blockDim.x + threadIdx.x) >> 5;
    const int e0   = warp * 8;                 // NEDGES % 8 == 0

    // 8 destination indices (two 16B broadcast loads)
    const int4 da = __ldg(reinterpret_cast<const int4*>(dst) + 2 * warp);
    const int4 db = __ldg(reinterpret_cast<const int4*>(dst) + 2 * warp + 1);
    const int d[8] = {da.x, da.y, da.z, da.w, db.x, db.y, db.z, db.w};

    // 16 row loads + 8 flag bytes, all independent and in flight together
    float4 ef[8], nd[8];
#pragma unroll
    for (int i = 0; i < 8; i++)
        ef[i] = __ldcs(reinterpret_cast<const float4*>(eft + (size_t)(e0 + i) * ROW) + lane);
#pragma unroll
    for (int i = 0; i < 8; i++)
        nd[i] = __ldg(reinterpret_cast<const float4*>(node + (size_t)d[i] * ROW) + lane);
    unsigned char fl[8];
#pragma unroll
    for (int i = 0; i < 8; i++) fl[i] = g_flag[d[i]];

    // 8 independent dot + head-softmax chains (shuffles overlap)
    float a[8];
#pragma unroll
    for (int i = 0; i < 8; i++) {
        float s = ef[i].x * nd[i].x + ef[i].y * nd[i].y
                + ef[i].z * nd[i].z + ef[i].w * nd[i].w;
        s += __shfl_xor_sync(0xFFFFFFFFu, s, 1);
        s += __shfl_xor_sync(0xFFFFFFFFu, s, 2);     // sim[head] in 4-lane group
        float ex  = __expf(s);                       // |sim| small: no max-sub
        float sum = ex;
        sum += __shfl_xor_sync(0xFFFFFFFFu, sum, 4);
        sum += __shfl_xor_sync(0xFFFFFFFFu, sum, 8);
        sum += __shfl_xor_sync(0xFFFFFFFFu, sum, 16);  // over all 8 heads
        a[i] = ex / sum;
    }

    // a output: warp covers a[e0*8 .. e0*8+63] -> two coalesced 128B lines.
    // line 0: edges 0..3, line 1: edges 4..7. lane -> slot s=lane&3, head h=lane>>2.
    {
        const int s = lane & 3, h = lane >> 2;
        float v0 = a[0];
        v0 = (s == 1) ? a[1] : v0;
        v0 = (s == 2) ? a[2] : v0;
        v0 = (s == 3) ? a[3] : v0;
        float v1 = a[4];
        v1 = (s == 1) ? a[5] : v1;
        v1 = (s == 2) ? a[6] : v1;
        v1 = (s == 3) ? a[7] : v1;
        a_out[(size_t)warp * 64 + s * 8 + h]      = v0;
        a_out[(size_t)warp * 64 + 32 + s * 8 + h] = v1;
    }

    // scatter only into target nodes (~18% of edges); each RED covers the
    // edge's contiguous 512B row (4 lines), fire-and-forget.
#pragma unroll
    for (int i = 0; i < 8; i++) {
        if (fl[i]) {
            float* p = &g_nft[(size_t)d[i] * ROW + lane * 4];
            asm volatile("red.global.add.v4.f32 [%0], {%1,%2,%3,%4};"
                         :: "l"(p),
                            "f"(ef[i].x * a[i]), "f"(ef[i].y * a[i]),
                            "f"(ef[i].z * a[i]), "f"(ef[i].w * a[i])
                         : "memory");
        }
    }
}

// ---------------------------------------------------------------------------
// K3: gather targets, +1e-15, L2-normalize over heads per (t, d), write out.
// 1 warp per target.
// ---------------------------------------------------------------------------
__global__ void k_out(const int* __restrict__ target_idx,
                      float* __restrict__ out, int T) {
    int w = (blockIdx.x * blockDim.x + threadIdx.x) >> 5;
    if (w >= T) return;
    int lane = threadIdx.x & 31;
    int n = target_idx[w];

    float4 x = *reinterpret_cast<const float4*>(&g_nft[(size_t)n * ROW + lane * 4]);
    x.x += 1e-15f; x.y += 1e-15f; x.z += 1e-15f; x.w += 1e-15f;

    float4 sq = make_float4(x.x * x.x, x.y * x.y, x.z * x.z, x.w * x.w);
#pragma unroll
    for (int off = 4; off <= 16; off <<= 1) {
        sq.x += __shfl_xor_sync(0xFFFFFFFFu, sq.x, off);
        sq.y += __shfl_xor_sync(0xFFFFFFFFu, sq.y, off);
        sq.z += __shfl_xor_sync(0xFFFFFFFFu, sq.z, off);
        sq.w += __shfl_xor_sync(0xFFFFFFFFu, sq.w, off);
    }
    float4 r;
    r.x = x.x / fmaxf(sqrtf(sq.x), 1e-12f);
    r.y = x.y / fmaxf(sqrtf(sq.y), 1e-12f);
    r.z = x.z / fmaxf(sqrtf(sq.z), 1e-12f);
    r.w = x.w / fmaxf(sqrtf(sq.w), 1e-12f);

    *reinterpret_cast<float4*>(&out[(size_t)w * ROW + lane * 4]) = r;
}

// ---------------------------------------------------------------------------
// Inputs (metadata order): node [N,H,D] f32, eft [E,H,D] f32, dst [E] i32,
// target_idx [T] i32. Output: concat(out [T,H,D], a [E,H]) as f32.
// ---------------------------------------------------------------------------
extern "C" void kernel_launch(void* const* d_in, const int* in_sizes, int n_in,
                              void* d_out, int out_size) {
    const float* node       = (const float*)d_in[0];
    const float* eft        = (const float*)d_in[1];
    const int*   dst        = (const int*)d_in[2];
    const int*   target_idx = (const int*)d_in[3];

    float* out   = (float*)d_out;                       // [T,H,D]
    float* a_out = (float*)d_out + (size_t)NTGT * ROW;  // [E,H]

    // K1: 1 warp per target
    k_prep<<<(NTGT * 32 + 255) / 256, 256>>>(target_idx, NTGT);
    // K2: 8 edges per warp -> 64 edges per 256-thread block
    k_edge<<<NEDGES / 64, 256>>>(node, eft, dst, a_out);   // 600000 % 64 != 0? 600000/64=9375 exactly
    // K3: 1 warp per target
    k_out<<<(NTGT * 32 + 255) / 256, 256>>>(target_idx, out, NTGT);
}